// round 1
// baseline (speedup 1.0000x reference)
#include <cuda_runtime.h>

// ---------------------------------------------------------------------------
// GNN edge-MLP + segment-sum, GB300 sm_103a
// inputs: x[100000,64] f32, edge_index[2,1600000] i32, edge_attr[1600000,3] f32,
//         W1[131,64], b1[64], W2[64,128], b2[128]
// output: relu(segment_sum(mask * (relu([x_i|x_j|ea]@W1+b1)@W2+b2), dst)) [100000,128]
// ---------------------------------------------------------------------------

#define N_EDGES_MAX 1600000

__device__ int g_n_active;
__device__ int g_edge_list[N_EDGES_MAX];

// ---- packed f32x2 helpers (Blackwell FFMA2 path, PTX-only) ----------------
__device__ __forceinline__ unsigned long long pk2(float v) {
    unsigned int u = __float_as_uint(v);
    unsigned long long r;
    asm("mov.b64 %0, {%1, %2};" : "=l"(r) : "r"(u), "r"(u));
    return r;
}
__device__ __forceinline__ unsigned long long pkf(float lo, float hi) {
    unsigned long long r;
    asm("mov.b64 %0, {%1, %2};" : "=l"(r)
        : "r"(__float_as_uint(lo)), "r"(__float_as_uint(hi)));
    return r;
}
__device__ __forceinline__ void fma2(unsigned long long& d,
                                     unsigned long long a,
                                     unsigned long long b) {
    asm("fma.rn.f32x2 %0, %1, %2, %0;" : "+l"(d) : "l"(a), "l"(b));
}
__device__ __forceinline__ float2 unpk(unsigned long long v) {
    unsigned int lo, hi;
    asm("mov.b64 {%0, %1}, %2;" : "=r"(lo), "=r"(hi) : "l"(v));
    return make_float2(__uint_as_float(lo), __uint_as_float(hi));
}

// ---------------------------------------------------------------------------
__global__ void k_zero() { g_n_active = 0; }

// Mask + compaction: keep only edges whose message survives the range mask.
__global__ void k_compact(const int* __restrict__ ei,
                          const float* __restrict__ ea,
                          const float* __restrict__ x, int n_edges) {
    int e = blockIdx.x * blockDim.x + threadIdx.x;
    bool act = false;
    if (e < n_edges) {
        int src = ei[e];                       // x_j = x[src]
        float ntype = __ldg(&x[(size_t)src * 64]);
        float dist = __ldg(&ea[(size_t)e * 3]);
        act = (ntype == 0.0f) ? (dist < 0.5f)
            : (ntype == 1.0f) ? (dist < 0.3f)
                              : true;
    }
    unsigned m = __ballot_sync(0xffffffffu, act);
    int lane = threadIdx.x & 31;
    int base = 0;
    if (lane == 0) base = atomicAdd(&g_n_active, __popc(m));
    base = __shfl_sync(0xffffffffu, base, 0);
    if (act) {
        int rank = __popc(m & ((1u << lane) - 1u));
        g_edge_list[base + rank] = e;
    }
}

// ---------------------------------------------------------------------------
// Persistent fused MLP over 64-edge tiles. 128 threads/CTA, 2 CTA/SM.
// smem: W1s[131*64] W2s[64*128] Hs[131*64] b1s[64] b2s[128] dsts[64]
// GEMM1: thread (te=tid>>3, tn=tid&7) computes edges te*4..+3 x hidden
//        {tn*4..+3, 32+tn*4..+3} as 16 FFMA2/k.
// GEMM2: same layout over 2 halves of the 128 output columns.
// ---------------------------------------------------------------------------
__global__ __launch_bounds__(128) void k_mlp(
    const float* __restrict__ x, const int* __restrict__ ei,
    const float* __restrict__ ea,
    const float* __restrict__ W1, const float* __restrict__ b1,
    const float* __restrict__ W2, const float* __restrict__ b2,
    float* __restrict__ out, int n_edges)
{
    extern __shared__ float sm[];
    float* W1s = sm;                  // 131*64
    float* W2s = W1s + 131 * 64;      // 64*128
    float* Hs  = W2s + 64 * 128;      // 131*64 (reused as Hid[64][64] after GEMM1)
    float* b1s = Hs + 131 * 64;       // 64
    float* b2s = b1s + 64;            // 128
    int*   dsts = (int*)(b2s + 128);  // 64

    const int tid = threadIdx.x;
    for (int i = tid; i < 131 * 64; i += 128) W1s[i] = W1[i];
    for (int i = tid; i < 64 * 128; i += 128) W2s[i] = W2[i];
    if (tid < 64) b1s[tid] = b1[tid];
    b2s[tid] = b2[tid];
    __syncthreads();

    const int tn = tid & 7;
    const int te = tid >> 3;
    const int e_loc = tid & 63;
    const int c = tid >> 6;   // 0,1 : which half of the 64-float x row we stage

    // bias pairs (hoisted; edge-independent)
    unsigned long long b1p[4], b2p[2][4];
    b1p[0] = pkf(b1s[tn * 4 + 0], b1s[tn * 4 + 1]);
    b1p[1] = pkf(b1s[tn * 4 + 2], b1s[tn * 4 + 3]);
    b1p[2] = pkf(b1s[32 + tn * 4 + 0], b1s[32 + tn * 4 + 1]);
    b1p[3] = pkf(b1s[32 + tn * 4 + 2], b1s[32 + tn * 4 + 3]);
#pragma unroll
    for (int h = 0; h < 2; h++) {
        const float* bb = b2s + h * 64;
        b2p[h][0] = pkf(bb[tn * 4 + 0], bb[tn * 4 + 1]);
        b2p[h][1] = pkf(bb[tn * 4 + 2], bb[tn * 4 + 3]);
        b2p[h][2] = pkf(bb[32 + tn * 4 + 0], bb[32 + tn * 4 + 1]);
        b2p[h][3] = pkf(bb[32 + tn * 4 + 2], bb[32 + tn * 4 + 3]);
    }

    const int n_act = g_n_active;

    for (int tile = blockIdx.x; tile * 64 < n_act; tile += gridDim.x) {
        const int base = tile * 64;
        int nt = n_act - base;
        if (nt > 64) nt = 64;

        __syncthreads();   // previous tile's Hid/dsts no longer in use

        // ---- stage H transposed: Hs[k][edge], k: 0..63 x_i, 64..127 x_j, 128..130 ea
        {
            int sl = (e_loc < nt) ? e_loc : 0;   // clamp; invalid slots skipped at scatter
            int eid = g_edge_list[base + sl];
            int src = __ldg(&ei[eid]);
            int dst = __ldg(&ei[n_edges + eid]);
            if (c == 0) dsts[e_loc] = dst;
            const float4* xi = (const float4*)(x + (size_t)dst * 64) + c * 8;
            const float4* xj = (const float4*)(x + (size_t)src * 64) + c * 8;
#pragma unroll
            for (int q = 0; q < 8; q++) {
                float4 v = __ldg(&xi[q]);
                int k0 = c * 32 + q * 4;
                Hs[(k0 + 0) * 64 + e_loc] = v.x;
                Hs[(k0 + 1) * 64 + e_loc] = v.y;
                Hs[(k0 + 2) * 64 + e_loc] = v.z;
                Hs[(k0 + 3) * 64 + e_loc] = v.w;
            }
#pragma unroll
            for (int q = 0; q < 8; q++) {
                float4 v = __ldg(&xj[q]);
                int k0 = 64 + c * 32 + q * 4;
                Hs[(k0 + 0) * 64 + e_loc] = v.x;
                Hs[(k0 + 1) * 64 + e_loc] = v.y;
                Hs[(k0 + 2) * 64 + e_loc] = v.z;
                Hs[(k0 + 3) * 64 + e_loc] = v.w;
            }
            if (c == 0) {
                const float* e3 = ea + (size_t)eid * 3;
                Hs[128 * 64 + e_loc] = __ldg(&e3[0]);
                Hs[129 * 64 + e_loc] = __ldg(&e3[1]);
                Hs[130 * 64 + e_loc] = __ldg(&e3[2]);
            }
        }
        __syncthreads();

        // ---- GEMM1: hidden[64 edges x 64] = H[64x131] @ W1[131x64] (+b1), relu
        unsigned long long acc[4][4];
#pragma unroll
        for (int e = 0; e < 4; e++)
#pragma unroll
            for (int p = 0; p < 4; p++) acc[e][p] = b1p[p];

#pragma unroll 4
        for (int k = 0; k < 131; k++) {
            float4 h4 = *(const float4*)(Hs + k * 64 + te * 4);
            const float* wrow = W1s + k * 64;
            ulonglong2 wA = *(const ulonglong2*)(wrow + tn * 4);
            ulonglong2 wB = *(const ulonglong2*)(wrow + 32 + tn * 4);
            unsigned long long hd0 = pk2(h4.x), hd1 = pk2(h4.y),
                               hd2 = pk2(h4.z), hd3 = pk2(h4.w);
            fma2(acc[0][0], hd0, wA.x); fma2(acc[0][1], hd0, wA.y);
            fma2(acc[0][2], hd0, wB.x); fma2(acc[0][3], hd0, wB.y);
            fma2(acc[1][0], hd1, wA.x); fma2(acc[1][1], hd1, wA.y);
            fma2(acc[1][2], hd1, wB.x); fma2(acc[1][3], hd1, wB.y);
            fma2(acc[2][0], hd2, wA.x); fma2(acc[2][1], hd2, wA.y);
            fma2(acc[2][2], hd2, wB.x); fma2(acc[2][3], hd2, wB.y);
            fma2(acc[3][0], hd3, wA.x); fma2(acc[3][1], hd3, wA.y);
            fma2(acc[3][2], hd3, wB.x); fma2(acc[3][3], hd3, wB.y);
        }
        __syncthreads();   // everyone done reading Hs

        // relu + store hidden transposed into Hid (= Hs rows 0..63)
#pragma unroll
        for (int e = 0; e < 4; e++) {
            int ecol = te * 4 + e;
#pragma unroll
            for (int p = 0; p < 4; p++) {
                float2 v = unpk(acc[e][p]);
                int h = (p < 2) ? (tn * 4 + p * 2) : (32 + tn * 4 + (p - 2) * 2);
                Hs[h * 64 + ecol] = fmaxf(v.x, 0.0f);
                Hs[(h + 1) * 64 + ecol] = fmaxf(v.y, 0.0f);
            }
        }
        __syncthreads();

        // ---- GEMM2 (+b2) and fused atomic scatter, two 64-col halves
#pragma unroll
        for (int half = 0; half < 2; half++) {
            unsigned long long a2[4][4];
#pragma unroll
            for (int e = 0; e < 4; e++)
#pragma unroll
                for (int p = 0; p < 4; p++) a2[e][p] = b2p[half][p];

#pragma unroll 4
            for (int k = 0; k < 64; k++) {
                float4 h4 = *(const float4*)(Hs + k * 64 + te * 4);
                const float* wrow = W2s + k * 128 + half * 64;
                ulonglong2 wA = *(const ulonglong2*)(wrow + tn * 4);
                ulonglong2 wB = *(const ulonglong2*)(wrow + 32 + tn * 4);
                unsigned long long hd0 = pk2(h4.x), hd1 = pk2(h4.y),
                                   hd2 = pk2(h4.z), hd3 = pk2(h4.w);
                fma2(a2[0][0], hd0, wA.x); fma2(a2[0][1], hd0, wA.y);
                fma2(a2[0][2], hd0, wB.x); fma2(a2[0][3], hd0, wB.y);
                fma2(a2[1][0], hd1, wA.x); fma2(a2[1][1], hd1, wA.y);
                fma2(a2[1][2], hd1, wB.x); fma2(a2[1][3], hd1, wB.y);
                fma2(a2[2][0], hd2, wA.x); fma2(a2[2][1], hd2, wA.y);
                fma2(a2[2][2], hd2, wB.x); fma2(a2[2][3], hd2, wB.y);
                fma2(a2[3][0], hd3, wA.x); fma2(a2[3][1], hd3, wA.y);
                fma2(a2[3][2], hd3, wB.x); fma2(a2[3][3], hd3, wB.y);
            }

#pragma unroll
            for (int e = 0; e < 4; e++) {
                int ecol = te * 4 + e;
                if (ecol < nt) {
                    int d = dsts[ecol];
                    float* op = out + (size_t)d * 128 + half * 64;
#pragma unroll
                    for (int p = 0; p < 4; p++) {
                        float2 v = unpk(a2[e][p]);
                        int cc = (p < 2) ? (tn * 4 + p * 2)
                                         : (32 + tn * 4 + (p - 2) * 2);
                        atomicAdd(op + cc, v.x);       // return unused -> RED
                        atomicAdd(op + cc + 1, v.y);
                    }
                }
            }
        }
    }
}

// ---------------------------------------------------------------------------
__global__ void k_relu(float4* __restrict__ out, int n4) {
    int i = blockIdx.x * blockDim.x + threadIdx.x;
    if (i < n4) {
        float4 v = out[i];
        v.x = fmaxf(v.x, 0.0f);
        v.y = fmaxf(v.y, 0.0f);
        v.z = fmaxf(v.z, 0.0f);
        v.w = fmaxf(v.w, 0.0f);
        out[i] = v;
    }
}

// ---------------------------------------------------------------------------
extern "C" void kernel_launch(void* const* d_in, const int* in_sizes, int n_in,
                              void* d_out, int out_size) {
    const float* x  = (const float*)d_in[0];
    const int*   ei = (const int*)d_in[1];
    const float* ea = (const float*)d_in[2];
    const float* W1 = (const float*)d_in[3];
    const float* b1 = (const float*)d_in[4];
    const float* W2 = (const float*)d_in[5];
    const float* b2 = (const float*)d_in[6];
    float* out = (float*)d_out;

    const int n_edges = in_sizes[1] / 2;
    const int smem_bytes = (131 * 64 + 64 * 128 + 131 * 64 + 64 + 128) * 4 + 64 * 4;

    cudaFuncSetAttribute(k_mlp, cudaFuncAttributeMaxDynamicSharedMemorySize,
                         smem_bytes);

    cudaMemsetAsync(d_out, 0, (size_t)out_size * sizeof(float));
    k_zero<<<1, 1>>>();
    k_compact<<<(n_edges + 255) / 256, 256>>>(ei, ea, x, n_edges);
    k_mlp<<<304, 128, smem_bytes>>>(x, ei, ea, W1, b1, W2, b2, out, n_edges);

    const int n4 = out_size / 4;
    k_relu<<<(n4 + 255) / 256, 256>>>((float4*)d_out, n4);
}

// round 2
// speedup vs baseline: 2.5744x; 2.5744x over previous
#include <cuda_runtime.h>

// ---------------------------------------------------------------------------
// GNN edge-MLP + segment-sum, GB300 sm_103a — factored formulation
//   P[n] = x[n]@W1[0:64]   + b1        (dst contribution, b1 folded)
//   Q[n] = x[n]@W1[64:128]             (src contribution)
//   hid_e = relu(P[dst] + Q[src] + ea@W1[128:131])        (active edges only)
//   hidsum[d] = sum_e hid_e ; cnt[d] = #active edges
//   out[d] = relu(hidsum[d]@W2 + cnt[d]*b2)
// ---------------------------------------------------------------------------

#define N_NODES_C 100000
#define N_EDGES_MAX 1600000

__device__ int   g_n_active;
__device__ int   g_edge_list[N_EDGES_MAX];
__device__ float g_P[N_NODES_C * 64];
__device__ float g_Q[N_NODES_C * 64];
__device__ float g_hid[N_NODES_C * 64];
__device__ int   g_cnt[N_NODES_C];

// ---- packed f32x2 helpers --------------------------------------------------
__device__ __forceinline__ unsigned long long pk2(float v) {
    unsigned int u = __float_as_uint(v);
    unsigned long long r;
    asm("mov.b64 %0, {%1, %2};" : "=l"(r) : "r"(u), "r"(u));
    return r;
}
__device__ __forceinline__ unsigned long long pkf(float lo, float hi) {
    unsigned long long r;
    asm("mov.b64 %0, {%1, %2};" : "=l"(r)
        : "r"(__float_as_uint(lo)), "r"(__float_as_uint(hi)));
    return r;
}
__device__ __forceinline__ void fma2(unsigned long long& d,
                                     unsigned long long a,
                                     unsigned long long b) {
    asm("fma.rn.f32x2 %0, %1, %2, %0;" : "+l"(d) : "l"(a), "l"(b));
}
__device__ __forceinline__ float2 unpk(unsigned long long v) {
    unsigned int lo, hi;
    asm("mov.b64 {%0, %1}, %2;" : "=r"(lo), "=r"(hi) : "l"(v));
    return make_float2(__uint_as_float(lo), __uint_as_float(hi));
}

// ---------------------------------------------------------------------------
__global__ void k_zero_all() {
    int i = blockIdx.x * blockDim.x + threadIdx.x;
    int stride = gridDim.x * blockDim.x;
    float4 z = make_float4(0.f, 0.f, 0.f, 0.f);
    for (int j = i; j < N_NODES_C * 16; j += stride) ((float4*)g_hid)[j] = z;
    for (int j = i; j < N_NODES_C; j += stride) g_cnt[j] = 0;
    if (i == 0) g_n_active = 0;
}

// ---- mask + compaction -----------------------------------------------------
__global__ void k_compact(const int* __restrict__ ei,
                          const float* __restrict__ ea,
                          const float* __restrict__ x, int n_edges) {
    int e = blockIdx.x * blockDim.x + threadIdx.x;
    bool act = false;
    if (e < n_edges) {
        int src = ei[e];
        float ntype = __ldg(&x[(size_t)src * 64]);
        float dist = __ldg(&ea[(size_t)e * 3]);
        act = (ntype == 0.0f) ? (dist < 0.5f)
            : (ntype == 1.0f) ? (dist < 0.3f)
                              : true;
    }
    unsigned m = __ballot_sync(0xffffffffu, act);
    int lane = threadIdx.x & 31;
    int base = 0;
    if (lane == 0) base = atomicAdd(&g_n_active, __popc(m));
    base = __shfl_sync(0xffffffffu, base, 0);
    if (act) {
        int rank = __popc(m & ((1u << lane) - 1u));
        g_edge_list[base + rank] = e;
    }
}

// ---- per-node precompute: P = x@W1a + b1, Q = x@W1b ------------------------
// one warp per node; lane handles column pair {2*lane, 2*lane+1}
__global__ __launch_bounds__(256) void k_nodepre(
    const float* __restrict__ x, const float* __restrict__ W1,
    const float* __restrict__ b1)
{
    __shared__ unsigned long long ws[128 * 32];   // W1 rows 0..127 as col-pairs
    int tid = threadIdx.x;
    for (int i = tid; i < 128 * 32; i += 256) {
        float2 v = ((const float2*)W1)[i];
        ws[i] = pkf(v.x, v.y);
    }
    __syncthreads();

    int lane = tid & 31, wid = tid >> 5;
    unsigned long long bp = pkf(__ldg(&b1[2 * lane]), __ldg(&b1[2 * lane + 1]));
    int gw = blockIdx.x * 8 + wid, nw = gridDim.x * 8;

    for (int n = gw; n < N_NODES_C; n += nw) {
        const float* xr = x + (size_t)n * 64;
        unsigned long long aP = bp, aQ = 0ull;
#pragma unroll 8
        for (int k = 0; k < 64; k++) {
            unsigned long long xk = pk2(__ldg(xr + k));
            fma2(aP, xk, ws[k * 32 + lane]);
            fma2(aQ, xk, ws[(64 + k) * 32 + lane]);
        }
        float2 vP = unpk(aP), vQ = unpk(aQ);
        ((float2*)(g_P + (size_t)n * 64))[lane] = vP;
        ((float2*)(g_Q + (size_t)n * 64))[lane] = vQ;
    }
}

// ---- edge phase: hid = relu(P[dst]+Q[src]+ea@W1c), v4-RED scatter ----------
// 8 threads per edge (cg = lane&7 -> 8 cols each), 4 edges per warp
__global__ __launch_bounds__(256) void k_edge(
    const int* __restrict__ ei, const float* __restrict__ ea,
    const float* __restrict__ W1, int n_edges)
{
    __shared__ float wc[3 * 64];
    int tid = threadIdx.x;
    if (tid < 192) wc[tid] = W1[128 * 64 + tid];
    __syncthreads();

    int lane = tid & 31, wid = tid >> 5;
    int esub = lane >> 3, cg = lane & 7;
    float wcr[3][8];
#pragma unroll
    for (int r = 0; r < 3; r++)
#pragma unroll
        for (int j = 0; j < 8; j++) wcr[r][j] = wc[r * 64 + cg * 8 + j];

    const int n_act = g_n_active;
    int gw = blockIdx.x * 8 + wid, nw = gridDim.x * 8;

    for (int base = gw * 4; base < n_act; base += nw * 4) {
        int e = base + esub;
        if (e < n_act) {
            int eid = g_edge_list[e];
            int src = __ldg(ei + eid);
            int dst = __ldg(ei + n_edges + eid);
            const float* er = ea + (size_t)eid * 3;
            float e0 = __ldg(er), e1 = __ldg(er + 1), e2 = __ldg(er + 2);
            const float4* pp = (const float4*)(g_P + (size_t)dst * 64 + cg * 8);
            const float4* qq = (const float4*)(g_Q + (size_t)src * 64 + cg * 8);
            float4 p0 = pp[0], p1 = pp[1];
            float4 q0 = qq[0], q1 = qq[1];
            float t[8];
            t[0] = p0.x + q0.x; t[1] = p0.y + q0.y;
            t[2] = p0.z + q0.z; t[3] = p0.w + q0.w;
            t[4] = p1.x + q1.x; t[5] = p1.y + q1.y;
            t[6] = p1.z + q1.z; t[7] = p1.w + q1.w;
#pragma unroll
            for (int j = 0; j < 8; j++) {
                t[j] = fmaf(e0, wcr[0][j],
                       fmaf(e1, wcr[1][j],
                       fmaf(e2, wcr[2][j], t[j])));
                t[j] = fmaxf(t[j], 0.0f);
            }
            float* hb = g_hid + (size_t)dst * 64 + cg * 8;
            asm volatile("red.global.add.v4.f32 [%0], {%1,%2,%3,%4};"
                         :: "l"(hb), "f"(t[0]), "f"(t[1]), "f"(t[2]), "f"(t[3])
                         : "memory");
            asm volatile("red.global.add.v4.f32 [%0], {%1,%2,%3,%4};"
                         :: "l"(hb + 4), "f"(t[4]), "f"(t[5]), "f"(t[6]), "f"(t[7])
                         : "memory");
            if (cg == 0) atomicAdd(g_cnt + dst, 1);
        }
    }
}

// ---- per-node output: out = relu(hidsum@W2 + cnt*b2) -----------------------
// one warp per node; lane handles col-pairs {lane} and {32+lane} of 64 pairs
__global__ __launch_bounds__(256) void k_out(
    const float* __restrict__ W2, const float* __restrict__ b2,
    float* __restrict__ out)
{
    __shared__ unsigned long long ws[64 * 64];    // W2 as col-pairs
    __shared__ float b2s[128];
    int tid = threadIdx.x;
    for (int i = tid; i < 64 * 64; i += 256) {
        float2 v = ((const float2*)W2)[i];
        ws[i] = pkf(v.x, v.y);
    }
    if (tid < 128) b2s[tid] = b2[tid];
    __syncthreads();

    int lane = tid & 31, wid = tid >> 5;
    int gw = blockIdx.x * 8 + wid, nw = gridDim.x * 8;

    for (int n = gw; n < N_NODES_C; n += nw) {
        const float* hr = g_hid + (size_t)n * 64;
        float cf = (float)g_cnt[n];
        unsigned long long a0 = 0ull, a1 = 0ull;
#pragma unroll 8
        for (int k = 0; k < 64; k++) {
            unsigned long long hk = pk2(hr[k]);
            fma2(a0, hk, ws[k * 64 + lane]);
            fma2(a1, hk, ws[k * 64 + 32 + lane]);
        }
        float2 v0 = unpk(a0), v1 = unpk(a1);
        float2 r0, r1;
        r0.x = fmaxf(v0.x + cf * b2s[2 * lane], 0.0f);
        r0.y = fmaxf(v0.y + cf * b2s[2 * lane + 1], 0.0f);
        r1.x = fmaxf(v1.x + cf * b2s[64 + 2 * lane], 0.0f);
        r1.y = fmaxf(v1.y + cf * b2s[64 + 2 * lane + 1], 0.0f);
        float2* orow = (float2*)(out + (size_t)n * 128);
        orow[lane] = r0;
        orow[32 + lane] = r1;
    }
}

// ---------------------------------------------------------------------------
extern "C" void kernel_launch(void* const* d_in, const int* in_sizes, int n_in,
                              void* d_out, int out_size) {
    const float* x  = (const float*)d_in[0];
    const int*   ei = (const int*)d_in[1];
    const float* ea = (const float*)d_in[2];
    const float* W1 = (const float*)d_in[3];
    const float* b1 = (const float*)d_in[4];
    const float* W2 = (const float*)d_in[5];
    const float* b2 = (const float*)d_in[6];
    float* out = (float*)d_out;

    const int n_edges = in_sizes[1] / 2;

    k_zero_all<<<1024, 256>>>();
    k_compact<<<(n_edges + 255) / 256, 256>>>(ei, ea, x, n_edges);
    k_nodepre<<<608, 256>>>(x, W1, b1);
    k_edge<<<608, 256>>>(ei, ea, W1, n_edges);
    k_out<<<608, 256>>>(W2, b2, out);
}

// round 3
// speedup vs baseline: 2.7143x; 1.0543x over previous
#include <cuda_runtime.h>

// ---------------------------------------------------------------------------
// GNN edge-MLP + segment-sum, GB300 sm_103a — factored formulation
//   P[n] = x[n]@W1[0:64]   + b1
//   Q[n] = x[n]@W1[64:128]
//   hid_e = relu(P[dst] + Q[src] + ea@W1[128:131])   (active edges only)
//   hidsum[d] = sum hid_e ; cnt[d] = #active
//   out[d] = relu(hidsum[d]@W2 + cnt[d]*b2)
// Node GEMMs are 64-node register-tiled (16 FFMA2 per 3 LDS.128).
// ---------------------------------------------------------------------------

#define N_NODES_C 100000
#define N_EDGES_MAX 1600000

__device__ int   g_n_active;
__device__ int   g_edge_list[N_EDGES_MAX];
__device__ float g_P[N_NODES_C * 64];
__device__ float g_Q[N_NODES_C * 64];
__device__ float g_hid[N_NODES_C * 64];
__device__ int   g_cnt[N_NODES_C];

// ---- packed f32x2 helpers --------------------------------------------------
__device__ __forceinline__ unsigned long long pk2(float v) {
    unsigned int u = __float_as_uint(v);
    unsigned long long r;
    asm("mov.b64 %0, {%1, %2};" : "=l"(r) : "r"(u), "r"(u));
    return r;
}
__device__ __forceinline__ unsigned long long pkf(float lo, float hi) {
    unsigned long long r;
    asm("mov.b64 %0, {%1, %2};" : "=l"(r)
        : "r"(__float_as_uint(lo)), "r"(__float_as_uint(hi)));
    return r;
}
__device__ __forceinline__ void fma2(unsigned long long& d,
                                     unsigned long long a,
                                     unsigned long long b) {
    asm("fma.rn.f32x2 %0, %1, %2, %0;" : "+l"(d) : "l"(a), "l"(b));
}
__device__ __forceinline__ float2 unpk(unsigned long long v) {
    unsigned int lo, hi;
    asm("mov.b64 {%0, %1}, %2;" : "=r"(lo), "=r"(hi) : "l"(v));
    return make_float2(__uint_as_float(lo), __uint_as_float(hi));
}

// ---------------------------------------------------------------------------
__global__ void k_zero_all() {
    int i = blockIdx.x * blockDim.x + threadIdx.x;
    int stride = gridDim.x * blockDim.x;
    float4 z = make_float4(0.f, 0.f, 0.f, 0.f);
    for (int j = i; j < N_NODES_C * 16; j += stride) ((float4*)g_hid)[j] = z;
    for (int j = i; j < N_NODES_C; j += stride) g_cnt[j] = 0;
    if (i == 0) g_n_active = 0;
}

// ---- mask + compaction -----------------------------------------------------
__global__ void k_compact(const int* __restrict__ ei,
                          const float* __restrict__ ea,
                          const float* __restrict__ x, int n_edges) {
    int e = blockIdx.x * blockDim.x + threadIdx.x;
    bool act = false;
    if (e < n_edges) {
        int src = ei[e];
        float ntype = __ldg(&x[(size_t)src * 64]);
        float dist = __ldg(&ea[(size_t)e * 3]);
        act = (ntype == 0.0f) ? (dist < 0.5f)
            : (ntype == 1.0f) ? (dist < 0.3f)
                              : true;
    }
    unsigned m = __ballot_sync(0xffffffffu, act);
    int lane = threadIdx.x & 31;
    int base = 0;
    if (lane == 0) base = atomicAdd(&g_n_active, __popc(m));
    base = __shfl_sync(0xffffffffu, base, 0);
    if (act) {
        int rank = __popc(m & ((1u << lane) - 1u));
        g_edge_list[base + rank] = e;
    }
}

// ---------------------------------------------------------------------------
// Node precompute GEMM: [P|Q][64 nodes x 128] = X[64x64] @ Wc[64x128]
// Wc[k][j] = W1[k][j] (j<64, P) / W1[64+k][j-64] (j>=64, Q). b1 folded into P.
// 128 threads; thread (te=tid>>3, tn=tid&7): nodes te*4..+3, cols
// {tn*4..+3, 32+tn*4..+3} of each 64-col half.
// ---------------------------------------------------------------------------
__global__ __launch_bounds__(128) void k_nodepre_t(
    const float* __restrict__ x, const float* __restrict__ W1,
    const float* __restrict__ b1)
{
    extern __shared__ float sm[];
    float* Wc = sm;            // 64*128
    float* Xt = Wc + 64 * 128; // 64k x 64n

    const int tid = threadIdx.x;
    for (int idx = tid; idx < 64 * 128; idx += 128) {
        int k = idx >> 7, j = idx & 127;
        Wc[idx] = (j < 64) ? W1[k * 64 + j] : W1[(64 + k) * 64 + (j - 64)];
    }
    __syncthreads();

    const int tn = tid & 7, te = tid >> 3;
    const int n_loc = tid & 63, c = tid >> 6;

    unsigned long long b1p[4];
    b1p[0] = pkf(__ldg(&b1[tn * 4 + 0]), __ldg(&b1[tn * 4 + 1]));
    b1p[1] = pkf(__ldg(&b1[tn * 4 + 2]), __ldg(&b1[tn * 4 + 3]));
    b1p[2] = pkf(__ldg(&b1[32 + tn * 4 + 0]), __ldg(&b1[32 + tn * 4 + 1]));
    b1p[3] = pkf(__ldg(&b1[32 + tn * 4 + 2]), __ldg(&b1[32 + tn * 4 + 3]));

    const int n_tiles = (N_NODES_C + 63) / 64;

    for (int tile = blockIdx.x; tile < n_tiles; tile += gridDim.x) {
        const int base = tile * 64;
        int nt = N_NODES_C - base;
        if (nt > 64) nt = 64;

        __syncthreads();
        {
            int n = base + ((n_loc < nt) ? n_loc : 0);
            const float4* xr = (const float4*)(x + (size_t)n * 64) + c * 8;
#pragma unroll
            for (int q = 0; q < 8; q++) {
                float4 v = __ldg(&xr[q]);
                int k0 = c * 32 + q * 4;
                Xt[(k0 + 0) * 64 + n_loc] = v.x;
                Xt[(k0 + 1) * 64 + n_loc] = v.y;
                Xt[(k0 + 2) * 64 + n_loc] = v.z;
                Xt[(k0 + 3) * 64 + n_loc] = v.w;
            }
        }
        __syncthreads();

#pragma unroll
        for (int half = 0; half < 2; half++) {
            unsigned long long acc[4][4];
#pragma unroll
            for (int e = 0; e < 4; e++)
#pragma unroll
                for (int p = 0; p < 4; p++)
                    acc[e][p] = half ? 0ull : b1p[p];

#pragma unroll 4
            for (int k = 0; k < 64; k++) {
                float4 h4 = *(const float4*)(Xt + k * 64 + te * 4);
                const float* wrow = Wc + k * 128 + half * 64;
                ulonglong2 wA = *(const ulonglong2*)(wrow + tn * 4);
                ulonglong2 wB = *(const ulonglong2*)(wrow + 32 + tn * 4);
                unsigned long long hd0 = pk2(h4.x), hd1 = pk2(h4.y),
                                   hd2 = pk2(h4.z), hd3 = pk2(h4.w);
                fma2(acc[0][0], hd0, wA.x); fma2(acc[0][1], hd0, wA.y);
                fma2(acc[0][2], hd0, wB.x); fma2(acc[0][3], hd0, wB.y);
                fma2(acc[1][0], hd1, wA.x); fma2(acc[1][1], hd1, wA.y);
                fma2(acc[1][2], hd1, wB.x); fma2(acc[1][3], hd1, wB.y);
                fma2(acc[2][0], hd2, wA.x); fma2(acc[2][1], hd2, wA.y);
                fma2(acc[2][2], hd2, wB.x); fma2(acc[2][3], hd2, wB.y);
                fma2(acc[3][0], hd3, wA.x); fma2(acc[3][1], hd3, wA.y);
                fma2(acc[3][2], hd3, wB.x); fma2(acc[3][3], hd3, wB.y);
            }

            float* dstbuf = half ? g_Q : g_P;
#pragma unroll
            for (int e = 0; e < 4; e++) {
                int nl = te * 4 + e;
                if (nl < nt) {
                    float* op = dstbuf + (size_t)(base + nl) * 64;
#pragma unroll
                    for (int p = 0; p < 4; p++) {
                        float2 v = unpk(acc[e][p]);
                        int cc = (p < 2) ? (tn * 4 + p * 2)
                                         : (32 + tn * 4 + (p - 2) * 2);
                        *(float2*)(op + cc) = v;
                    }
                }
            }
        }
    }
}

// ---- edge phase: hid = relu(P[dst]+Q[src]+ea@W1c), v4-RED scatter ----------
// 16 threads per edge (cg -> 4 cols), 2 edges per warp.
__global__ __launch_bounds__(256) void k_edge(
    const int* __restrict__ ei, const float* __restrict__ ea,
    const float* __restrict__ W1, int n_edges)
{
    __shared__ float wc[3 * 64];
    int tid = threadIdx.x;
    if (tid < 192) wc[tid] = W1[128 * 64 + tid];
    __syncthreads();

    int lane = tid & 31, wid = tid >> 5;
    int esub = lane >> 4, cg = lane & 15;
    float wcr[3][4];
#pragma unroll
    for (int r = 0; r < 3; r++)
#pragma unroll
        for (int j = 0; j < 4; j++) wcr[r][j] = wc[r * 64 + cg * 4 + j];

    const int n_act = g_n_active;
    int gw = blockIdx.x * 8 + wid, nw = gridDim.x * 8;

    for (int base = gw * 2; base < n_act; base += nw * 2) {
        int e = base + esub;
        if (e < n_act) {
            int eid = g_edge_list[e];
            int src = __ldg(ei + eid);
            int dst = __ldg(ei + n_edges + eid);
            const float* er = ea + (size_t)eid * 3;
            float e0 = __ldg(er), e1 = __ldg(er + 1), e2 = __ldg(er + 2);
            float4 p = ((const float4*)(g_P + (size_t)dst * 64))[cg];
            float4 q = ((const float4*)(g_Q + (size_t)src * 64))[cg];
            float t0 = p.x + q.x, t1 = p.y + q.y, t2 = p.z + q.z, t3 = p.w + q.w;
            t0 = fmaf(e0, wcr[0][0], fmaf(e1, wcr[1][0], fmaf(e2, wcr[2][0], t0)));
            t1 = fmaf(e0, wcr[0][1], fmaf(e1, wcr[1][1], fmaf(e2, wcr[2][1], t1)));
            t2 = fmaf(e0, wcr[0][2], fmaf(e1, wcr[1][2], fmaf(e2, wcr[2][2], t2)));
            t3 = fmaf(e0, wcr[0][3], fmaf(e1, wcr[1][3], fmaf(e2, wcr[2][3], t3)));
            t0 = fmaxf(t0, 0.0f); t1 = fmaxf(t1, 0.0f);
            t2 = fmaxf(t2, 0.0f); t3 = fmaxf(t3, 0.0f);
            float* hb = g_hid + (size_t)dst * 64 + cg * 4;
            asm volatile("red.global.add.v4.f32 [%0], {%1,%2,%3,%4};"
                         :: "l"(hb), "f"(t0), "f"(t1), "f"(t2), "f"(t3)
                         : "memory");
            if (cg == 0) atomicAdd(g_cnt + dst, 1);
        }
    }
}

// ---------------------------------------------------------------------------
// Output GEMM: out[64 nodes x 128] = relu(Hid[64x64] @ W2 + cnt*b2)
// ---------------------------------------------------------------------------
__global__ __launch_bounds__(128) void k_out_t(
    const float* __restrict__ W2, const float* __restrict__ b2,
    float* __restrict__ out)
{
    extern __shared__ float sm[];
    float* W2s = sm;             // 64*128
    float* Ht  = W2s + 64 * 128; // 64k x 64n
    float* cs  = Ht + 64 * 64;   // 64 counts
    float* b2s = cs + 64;        // 128

    const int tid = threadIdx.x;
    for (int idx = tid; idx < 64 * 128; idx += 128) W2s[idx] = W2[idx];
    b2s[tid] = b2[tid];
    __syncthreads();

    const int tn = tid & 7, te = tid >> 3;
    const int n_loc = tid & 63, c = tid >> 6;
    const int n_tiles = (N_NODES_C + 63) / 64;

    for (int tile = blockIdx.x; tile < n_tiles; tile += gridDim.x) {
        const int base = tile * 64;
        int nt = N_NODES_C - base;
        if (nt > 64) nt = 64;

        __syncthreads();
        {
            int n = base + ((n_loc < nt) ? n_loc : 0);
            const float4* hr = (const float4*)(g_hid + (size_t)n * 64) + c * 8;
#pragma unroll
            for (int q = 0; q < 8; q++) {
                float4 v = hr[q];
                int k0 = c * 32 + q * 4;
                Ht[(k0 + 0) * 64 + n_loc] = v.x;
                Ht[(k0 + 1) * 64 + n_loc] = v.y;
                Ht[(k0 + 2) * 64 + n_loc] = v.z;
                Ht[(k0 + 3) * 64 + n_loc] = v.w;
            }
            if (c == 0)
                cs[n_loc] = (n_loc < nt) ? (float)g_cnt[base + n_loc] : 0.0f;
        }
        __syncthreads();

#pragma unroll
        for (int half = 0; half < 2; half++) {
            unsigned long long acc[4][4];
#pragma unroll
            for (int e = 0; e < 4; e++)
#pragma unroll
                for (int p = 0; p < 4; p++) acc[e][p] = 0ull;

#pragma unroll 4
            for (int k = 0; k < 64; k++) {
                float4 h4 = *(const float4*)(Ht + k * 64 + te * 4);
                const float* wrow = W2s + k * 128 + half * 64;
                ulonglong2 wA = *(const ulonglong2*)(wrow + tn * 4);
                ulonglong2 wB = *(const ulonglong2*)(wrow + 32 + tn * 4);
                unsigned long long hd0 = pk2(h4.x), hd1 = pk2(h4.y),
                                   hd2 = pk2(h4.z), hd3 = pk2(h4.w);
                fma2(acc[0][0], hd0, wA.x); fma2(acc[0][1], hd0, wA.y);
                fma2(acc[0][2], hd0, wB.x); fma2(acc[0][3], hd0, wB.y);
                fma2(acc[1][0], hd1, wA.x); fma2(acc[1][1], hd1, wA.y);
                fma2(acc[1][2], hd1, wB.x); fma2(acc[1][3], hd1, wB.y);
                fma2(acc[2][0], hd2, wA.x); fma2(acc[2][1], hd2, wA.y);
                fma2(acc[2][2], hd2, wB.x); fma2(acc[2][3], hd2, wB.y);
                fma2(acc[3][0], hd3, wA.x); fma2(acc[3][1], hd3, wA.y);
                fma2(acc[3][2], hd3, wB.x); fma2(acc[3][3], hd3, wB.y);
            }

#pragma unroll
            for (int e = 0; e < 4; e++) {
                int nl = te * 4 + e;
                if (nl < nt) {
                    float cf = cs[nl];
                    float* op = out + (size_t)(base + nl) * 128 + half * 64;
#pragma unroll
                    for (int p = 0; p < 4; p++) {
                        float2 v = unpk(acc[e][p]);
                        int cc = (p < 2) ? (tn * 4 + p * 2)
                                         : (32 + tn * 4 + (p - 2) * 2);
                        float2 r;
                        r.x = fmaxf(v.x + cf * b2s[half * 64 + cc], 0.0f);
                        r.y = fmaxf(v.y + cf * b2s[half * 64 + cc + 1], 0.0f);
                        *(float2*)(op + cc) = r;
                    }
                }
            }
        }
    }
}

// ---------------------------------------------------------------------------
extern "C" void kernel_launch(void* const* d_in, const int* in_sizes, int n_in,
                              void* d_out, int out_size) {
    const float* x  = (const float*)d_in[0];
    const int*   ei = (const int*)d_in[1];
    const float* ea = (const float*)d_in[2];
    const float* W1 = (const float*)d_in[3];
    const float* b1 = (const float*)d_in[4];
    const float* W2 = (const float*)d_in[5];
    const float* b2 = (const float*)d_in[6];
    float* out = (float*)d_out;

    const int n_edges = in_sizes[1] / 2;

    const int smem_pre = (64 * 128 + 64 * 64) * 4;            // 49152
    const int smem_out = (64 * 128 + 64 * 64 + 64 + 128) * 4; // 49920
    cudaFuncSetAttribute(k_nodepre_t,
                         cudaFuncAttributeMaxDynamicSharedMemorySize, smem_pre);
    cudaFuncSetAttribute(k_out_t,
                         cudaFuncAttributeMaxDynamicSharedMemorySize, smem_out);

    k_zero_all<<<1024, 256>>>();
    k_compact<<<(n_edges + 255) / 256, 256>>>(ei, ea, x, n_edges);
    k_nodepre_t<<<592, 128, smem_pre>>>(x, W1, b1);
    k_edge<<<1184, 256>>>(ei, ea, W1, n_edges);
    k_out_t<<<592, 128, smem_out>>>(W2, b2, out);
}

// round 4
// speedup vs baseline: 5.2219x; 1.9239x over previous
#include <cuda_runtime.h>

// ---------------------------------------------------------------------------
// GNN edge-MLP + segment-sum, GB300 sm_103a — factored + CSR formulation
//   P[n] = x[n]@W1[0:64] + b1 ; Q[n] = x[n]@W1[64:128]
//   hid[d] = sum_{active e: dst=d} relu(P[d] + Q[src_e] + ea_e@W1[128:131])
//   out[d] = relu(hid[d]@W2 + cnt[d]*b2)
// Active edges bucketed by dst (hist -> scan -> place), then a per-node
// gather-reduce with zero atomics in the hot loop.
// ---------------------------------------------------------------------------

#define N_NODES_C 100000
#define N_EDGES_MAX 1600000
#define NPART 98   // ceil(100000/1024)

__device__ int    g_cnt[N_NODES_C];      // active-edge count per dst
__device__ int    g_off[N_NODES_C];      // CSR offsets (exclusive scan)
__device__ int    g_cur[N_NODES_C];      // placement cursors
__device__ int    g_part[NPART];         // scan partials
__device__ int    g_partoff[NPART];
__device__ unsigned g_maskbits[N_EDGES_MAX / 32];
__device__ int    g_esrc[N_EDGES_MAX];   // CSR: src per active edge
__device__ float4 g_eea[N_EDGES_MAX];    // CSR: (e0,e1,e2,-) per active edge
__device__ float  g_P[N_NODES_C * 64];
__device__ float  g_Q[N_NODES_C * 64];
__device__ float  g_hid[N_NODES_C * 64];

// ---- packed f32x2 helpers --------------------------------------------------
__device__ __forceinline__ unsigned long long pk2(float v) {
    unsigned int u = __float_as_uint(v);
    unsigned long long r;
    asm("mov.b64 %0, {%1, %2};" : "=l"(r) : "r"(u), "r"(u));
    return r;
}
__device__ __forceinline__ unsigned long long pkf(float lo, float hi) {
    unsigned long long r;
    asm("mov.b64 %0, {%1, %2};" : "=l"(r)
        : "r"(__float_as_uint(lo)), "r"(__float_as_uint(hi)));
    return r;
}
__device__ __forceinline__ void fma2(unsigned long long& d,
                                     unsigned long long a,
                                     unsigned long long b) {
    asm("fma.rn.f32x2 %0, %1, %2, %0;" : "+l"(d) : "l"(a), "l"(b));
}
__device__ __forceinline__ float2 unpk(unsigned long long v) {
    unsigned int lo, hi;
    asm("mov.b64 {%0, %1}, %2;" : "=r"(lo), "=r"(hi) : "l"(v));
    return make_float2(__uint_as_float(lo), __uint_as_float(hi));
}

// ---------------------------------------------------------------------------
__global__ void k_zero() {
    int i = blockIdx.x * blockDim.x + threadIdx.x;
    if (i < N_NODES_C) g_cnt[i] = 0;
}

// ---- histogram: mask + per-dst active count + mask bitmap ------------------
__global__ void k_hist(const int* __restrict__ ei,
                       const float* __restrict__ ea,
                       const float* __restrict__ x, int n_edges) {
    int e = blockIdx.x * blockDim.x + threadIdx.x;
    bool act = false;
    int dst = 0;
    if (e < n_edges) {
        int src = __ldg(ei + e);
        dst = __ldg(ei + n_edges + e);
        float ntype = __ldg(&x[(size_t)src * 64]);
        float dist = __ldg(&ea[(size_t)e * 3]);
        act = (ntype == 0.0f) ? (dist < 0.5f)
            : (ntype == 1.0f) ? (dist < 0.3f)
                              : true;
    }
    unsigned m = __ballot_sync(0xffffffffu, act);
    if ((threadIdx.x & 31) == 0) g_maskbits[e >> 5] = m;
    if (act) atomicAdd(g_cnt + dst, 1);
}

// ---- exclusive scan over g_cnt (1024-elem blocks) --------------------------
__global__ __launch_bounds__(1024) void k_scanA() {
    __shared__ int s[1024];
    int t = threadIdx.x;
    int i = blockIdx.x * 1024 + t;
    int v = (i < N_NODES_C) ? g_cnt[i] : 0;
    s[t] = v;
    __syncthreads();
#pragma unroll
    for (int d = 1; d < 1024; d <<= 1) {
        int u = (t >= d) ? s[t - d] : 0;
        __syncthreads();
        s[t] += u;
        __syncthreads();
    }
    if (i < N_NODES_C) g_off[i] = s[t] - v;       // exclusive within block
    if (t == 1023) g_part[blockIdx.x] = s[1023];  // block total
}

__global__ __launch_bounds__(128) void k_scanB() {
    __shared__ int s[128];
    int t = threadIdx.x;
    int v = (t < NPART) ? g_part[t] : 0;
    s[t] = v;
    __syncthreads();
#pragma unroll
    for (int d = 1; d < 128; d <<= 1) {
        int u = (t >= d) ? s[t - d] : 0;
        __syncthreads();
        s[t] += u;
        __syncthreads();
    }
    if (t < NPART) g_partoff[t] = s[t] - v;       // exclusive
}

__global__ __launch_bounds__(1024) void k_scanC() {
    int i = blockIdx.x * 1024 + threadIdx.x;
    if (i < N_NODES_C) {
        int o = g_off[i] + g_partoff[blockIdx.x];
        g_off[i] = o;
        g_cur[i] = o;
    }
}

// ---- CSR placement ---------------------------------------------------------
__global__ void k_place(const int* __restrict__ ei,
                        const float* __restrict__ ea, int n_edges) {
    int e = blockIdx.x * blockDim.x + threadIdx.x;
    if (e >= n_edges) return;
    unsigned w = g_maskbits[e >> 5];
    if ((w >> (e & 31)) & 1u) {
        int src = __ldg(ei + e);
        int dst = __ldg(ei + n_edges + e);
        const float* er = ea + (size_t)e * 3;
        int slot = atomicAdd(g_cur + dst, 1);
        g_esrc[slot] = src;
        g_eea[slot] = make_float4(__ldg(er), __ldg(er + 1), __ldg(er + 2), 0.f);
    }
}

// ---------------------------------------------------------------------------
// Node precompute GEMM: [P|Q][64 nodes x 128] = X[64x64] @ Wc[64x128]
// ---------------------------------------------------------------------------
__global__ __launch_bounds__(128) void k_nodepre_t(
    const float* __restrict__ x, const float* __restrict__ W1,
    const float* __restrict__ b1)
{
    extern __shared__ float sm[];
    float* Wc = sm;            // 64*128
    float* Xt = Wc + 64 * 128; // 64k x 64n

    const int tid = threadIdx.x;
    for (int idx = tid; idx < 64 * 128; idx += 128) {
        int k = idx >> 7, j = idx & 127;
        Wc[idx] = (j < 64) ? W1[k * 64 + j] : W1[(64 + k) * 64 + (j - 64)];
    }
    __syncthreads();

    const int tn = tid & 7, te = tid >> 3;
    const int n_loc = tid & 63, c = tid >> 6;

    unsigned long long b1p[4];
    b1p[0] = pkf(__ldg(&b1[tn * 4 + 0]), __ldg(&b1[tn * 4 + 1]));
    b1p[1] = pkf(__ldg(&b1[tn * 4 + 2]), __ldg(&b1[tn * 4 + 3]));
    b1p[2] = pkf(__ldg(&b1[32 + tn * 4 + 0]), __ldg(&b1[32 + tn * 4 + 1]));
    b1p[3] = pkf(__ldg(&b1[32 + tn * 4 + 2]), __ldg(&b1[32 + tn * 4 + 3]));

    const int n_tiles = (N_NODES_C + 63) / 64;

    for (int tile = blockIdx.x; tile < n_tiles; tile += gridDim.x) {
        const int base = tile * 64;
        int nt = N_NODES_C - base;
        if (nt > 64) nt = 64;

        __syncthreads();
        {
            int n = base + ((n_loc < nt) ? n_loc : 0);
            const float4* xr = (const float4*)(x + (size_t)n * 64) + c * 8;
#pragma unroll
            for (int q = 0; q < 8; q++) {
                float4 v = __ldg(&xr[q]);
                int k0 = c * 32 + q * 4;
                Xt[(k0 + 0) * 64 + n_loc] = v.x;
                Xt[(k0 + 1) * 64 + n_loc] = v.y;
                Xt[(k0 + 2) * 64 + n_loc] = v.z;
                Xt[(k0 + 3) * 64 + n_loc] = v.w;
            }
        }
        __syncthreads();

#pragma unroll
        for (int half = 0; half < 2; half++) {
            unsigned long long acc[4][4];
#pragma unroll
            for (int e = 0; e < 4; e++)
#pragma unroll
                for (int p = 0; p < 4; p++)
                    acc[e][p] = half ? 0ull : b1p[p];

#pragma unroll 4
            for (int k = 0; k < 64; k++) {
                float4 h4 = *(const float4*)(Xt + k * 64 + te * 4);
                const float* wrow = Wc + k * 128 + half * 64;
                ulonglong2 wA = *(const ulonglong2*)(wrow + tn * 4);
                ulonglong2 wB = *(const ulonglong2*)(wrow + 32 + tn * 4);
                unsigned long long hd0 = pk2(h4.x), hd1 = pk2(h4.y),
                                   hd2 = pk2(h4.z), hd3 = pk2(h4.w);
                fma2(acc[0][0], hd0, wA.x); fma2(acc[0][1], hd0, wA.y);
                fma2(acc[0][2], hd0, wB.x); fma2(acc[0][3], hd0, wB.y);
                fma2(acc[1][0], hd1, wA.x); fma2(acc[1][1], hd1, wA.y);
                fma2(acc[1][2], hd1, wB.x); fma2(acc[1][3], hd1, wB.y);
                fma2(acc[2][0], hd2, wA.x); fma2(acc[2][1], hd2, wA.y);
                fma2(acc[2][2], hd2, wB.x); fma2(acc[2][3], hd2, wB.y);
                fma2(acc[3][0], hd3, wA.x); fma2(acc[3][1], hd3, wA.y);
                fma2(acc[3][2], hd3, wB.x); fma2(acc[3][3], hd3, wB.y);
            }

            float* dstbuf = half ? g_Q : g_P;
#pragma unroll
            for (int e = 0; e < 4; e++) {
                int nl = te * 4 + e;
                if (nl < nt) {
                    float* op = dstbuf + (size_t)(base + nl) * 64;
#pragma unroll
                    for (int p = 0; p < 4; p++) {
                        float2 v = unpk(acc[e][p]);
                        int cc = (p < 2) ? (tn * 4 + p * 2)
                                         : (32 + tn * 4 + (p - 2) * 2);
                        *(float2*)(op + cc) = v;
                    }
                }
            }
        }
    }
}

// ---- gather-reduce: hid[d] = sum relu(P[d]+Q[src]+ea@W1c) ------------------
// 16 threads per node (cg -> 4 cols), 16 nodes per 256-thread block.
__global__ __launch_bounds__(256) void k_gather(
    const float* __restrict__ W1)
{
    __shared__ float wc[3 * 64];
    int tid = threadIdx.x;
    if (tid < 192) wc[tid] = W1[128 * 64 + tid];
    __syncthreads();

    int cg = tid & 15;
    int node = blockIdx.x * 16 + (tid >> 4);
    if (node >= N_NODES_C) return;

    float wcr[3][4];
#pragma unroll
    for (int r = 0; r < 3; r++)
#pragma unroll
        for (int j = 0; j < 4; j++) wcr[r][j] = wc[r * 64 + cg * 4 + j];

    int beg = g_off[node];
    int end = beg + g_cnt[node];
    float4 p = ((const float4*)(g_P + (size_t)node * 64))[cg];
    float a0 = 0.f, a1 = 0.f, a2 = 0.f, a3 = 0.f;

    int e = beg;
    for (; e + 2 <= end; e += 2) {
        int s0 = __ldg(g_esrc + e);
        int s1 = __ldg(g_esrc + e + 1);
        float4 A0 = __ldg(g_eea + e);
        float4 A1 = __ldg(g_eea + e + 1);
        float4 q0 = ((const float4*)(g_Q + (size_t)s0 * 64))[cg];
        float4 q1 = ((const float4*)(g_Q + (size_t)s1 * 64))[cg];

        float t0 = p.x + q0.x, t1 = p.y + q0.y, t2 = p.z + q0.z, t3 = p.w + q0.w;
        t0 = fmaf(A0.x, wcr[0][0], fmaf(A0.y, wcr[1][0], fmaf(A0.z, wcr[2][0], t0)));
        t1 = fmaf(A0.x, wcr[0][1], fmaf(A0.y, wcr[1][1], fmaf(A0.z, wcr[2][1], t1)));
        t2 = fmaf(A0.x, wcr[0][2], fmaf(A0.y, wcr[1][2], fmaf(A0.z, wcr[2][2], t2)));
        t3 = fmaf(A0.x, wcr[0][3], fmaf(A0.y, wcr[1][3], fmaf(A0.z, wcr[2][3], t3)));
        a0 += fmaxf(t0, 0.f); a1 += fmaxf(t1, 0.f);
        a2 += fmaxf(t2, 0.f); a3 += fmaxf(t3, 0.f);

        float u0 = p.x + q1.x, u1 = p.y + q1.y, u2 = p.z + q1.z, u3 = p.w + q1.w;
        u0 = fmaf(A1.x, wcr[0][0], fmaf(A1.y, wcr[1][0], fmaf(A1.z, wcr[2][0], u0)));
        u1 = fmaf(A1.x, wcr[0][1], fmaf(A1.y, wcr[1][1], fmaf(A1.z, wcr[2][1], u1)));
        u2 = fmaf(A1.x, wcr[0][2], fmaf(A1.y, wcr[1][2], fmaf(A1.z, wcr[2][2], u2)));
        u3 = fmaf(A1.x, wcr[0][3], fmaf(A1.y, wcr[1][3], fmaf(A1.z, wcr[2][3], u3)));
        a0 += fmaxf(u0, 0.f); a1 += fmaxf(u1, 0.f);
        a2 += fmaxf(u2, 0.f); a3 += fmaxf(u3, 0.f);
    }
    if (e < end) {
        int s0 = __ldg(g_esrc + e);
        float4 A0 = __ldg(g_eea + e);
        float4 q0 = ((const float4*)(g_Q + (size_t)s0 * 64))[cg];
        float t0 = p.x + q0.x, t1 = p.y + q0.y, t2 = p.z + q0.z, t3 = p.w + q0.w;
        t0 = fmaf(A0.x, wcr[0][0], fmaf(A0.y, wcr[1][0], fmaf(A0.z, wcr[2][0], t0)));
        t1 = fmaf(A0.x, wcr[0][1], fmaf(A0.y, wcr[1][1], fmaf(A0.z, wcr[2][1], t1)));
        t2 = fmaf(A0.x, wcr[0][2], fmaf(A0.y, wcr[1][2], fmaf(A0.z, wcr[2][2], t2)));
        t3 = fmaf(A0.x, wcr[0][3], fmaf(A0.y, wcr[1][3], fmaf(A0.z, wcr[2][3], t3)));
        a0 += fmaxf(t0, 0.f); a1 += fmaxf(t1, 0.f);
        a2 += fmaxf(t2, 0.f); a3 += fmaxf(t3, 0.f);
    }

    ((float4*)(g_hid + (size_t)node * 64))[cg] = make_float4(a0, a1, a2, a3);
}

// ---------------------------------------------------------------------------
// Output GEMM: out[64 nodes x 128] = relu(Hid[64x64] @ W2 + cnt*b2)
// ---------------------------------------------------------------------------
__global__ __launch_bounds__(128) void k_out_t(
    const float* __restrict__ W2, const float* __restrict__ b2,
    float* __restrict__ out)
{
    extern __shared__ float sm[];
    float* W2s = sm;             // 64*128
    float* Ht  = W2s + 64 * 128; // 64k x 64n
    float* cs  = Ht + 64 * 64;   // 64 counts
    float* b2s = cs + 64;        // 128

    const int tid = threadIdx.x;
    for (int idx = tid; idx < 64 * 128; idx += 128) W2s[idx] = W2[idx];
    b2s[tid] = b2[tid];
    __syncthreads();

    const int tn = tid & 7, te = tid >> 3;
    const int n_loc = tid & 63, c = tid >> 6;
    const int n_tiles = (N_NODES_C + 63) / 64;

    for (int tile = blockIdx.x; tile < n_tiles; tile += gridDim.x) {
        const int base = tile * 64;
        int nt = N_NODES_C - base;
        if (nt > 64) nt = 64;

        __syncthreads();
        {
            int n = base + ((n_loc < nt) ? n_loc : 0);
            const float4* hr = (const float4*)(g_hid + (size_t)n * 64) + c * 8;
#pragma unroll
            for (int q = 0; q < 8; q++) {
                float4 v = hr[q];
                int k0 = c * 32 + q * 4;
                Ht[(k0 + 0) * 64 + n_loc] = v.x;
                Ht[(k0 + 1) * 64 + n_loc] = v.y;
                Ht[(k0 + 2) * 64 + n_loc] = v.z;
                Ht[(k0 + 3) * 64 + n_loc] = v.w;
            }
            if (c == 0)
                cs[n_loc] = (n_loc < nt) ? (float)g_cnt[base + n_loc] : 0.0f;
        }
        __syncthreads();

#pragma unroll
        for (int half = 0; half < 2; half++) {
            unsigned long long acc[4][4];
#pragma unroll
            for (int e = 0; e < 4; e++)
#pragma unroll
                for (int p = 0; p < 4; p++) acc[e][p] = 0ull;

#pragma unroll 4
            for (int k = 0; k < 64; k++) {
                float4 h4 = *(const float4*)(Ht + k * 64 + te * 4);
                const float* wrow = W2s + k * 128 + half * 64;
                ulonglong2 wA = *(const ulonglong2*)(wrow + tn * 4);
                ulonglong2 wB = *(const ulonglong2*)(wrow + 32 + tn * 4);
                unsigned long long hd0 = pk2(h4.x), hd1 = pk2(h4.y),
                                   hd2 = pk2(h4.z), hd3 = pk2(h4.w);
                fma2(acc[0][0], hd0, wA.x); fma2(acc[0][1], hd0, wA.y);
                fma2(acc[0][2], hd0, wB.x); fma2(acc[0][3], hd0, wB.y);
                fma2(acc[1][0], hd1, wA.x); fma2(acc[1][1], hd1, wA.y);
                fma2(acc[1][2], hd1, wB.x); fma2(acc[1][3], hd1, wB.y);
                fma2(acc[2][0], hd2, wA.x); fma2(acc[2][1], hd2, wA.y);
                fma2(acc[2][2], hd2, wB.x); fma2(acc[2][3], hd2, wB.y);
                fma2(acc[3][0], hd3, wA.x); fma2(acc[3][1], hd3, wA.y);
                fma2(acc[3][2], hd3, wB.x); fma2(acc[3][3], hd3, wB.y);
            }

#pragma unroll
            for (int e = 0; e < 4; e++) {
                int nl = te * 4 + e;
                if (nl < nt) {
                    float cf = cs[nl];
                    float* op = out + (size_t)(base + nl) * 128 + half * 64;
#pragma unroll
                    for (int p = 0; p < 4; p++) {
                        float2 v = unpk(acc[e][p]);
                        int cc = (p < 2) ? (tn * 4 + p * 2)
                                         : (32 + tn * 4 + (p - 2) * 2);
                        float2 r;
                        r.x = fmaxf(v.x + cf * b2s[half * 64 + cc], 0.0f);
                        r.y = fmaxf(v.y + cf * b2s[half * 64 + cc + 1], 0.0f);
                        *(float2*)(op + cc) = r;
                    }
                }
            }
        }
    }
}

// ---------------------------------------------------------------------------
extern "C" void kernel_launch(void* const* d_in, const int* in_sizes, int n_in,
                              void* d_out, int out_size) {
    const float* x  = (const float*)d_in[0];
    const int*   ei = (const int*)d_in[1];
    const float* ea = (const float*)d_in[2];
    const float* W1 = (const float*)d_in[3];
    const float* b1 = (const float*)d_in[4];
    const float* W2 = (const float*)d_in[5];
    const float* b2 = (const float*)d_in[6];
    float* out = (float*)d_out;

    const int n_edges = in_sizes[1] / 2;

    const int smem_pre = (64 * 128 + 64 * 64) * 4;
    const int smem_out = (64 * 128 + 64 * 64 + 64 + 128) * 4;
    cudaFuncSetAttribute(k_nodepre_t,
                         cudaFuncAttributeMaxDynamicSharedMemorySize, smem_pre);
    cudaFuncSetAttribute(k_out_t,
                         cudaFuncAttributeMaxDynamicSharedMemorySize, smem_out);

    k_zero<<<(N_NODES_C + 255) / 256, 256>>>();
    k_hist<<<(n_edges + 255) / 256, 256>>>(ei, ea, x, n_edges);
    k_scanA<<<NPART, 1024>>>();
    k_scanB<<<1, 128>>>();
    k_scanC<<<NPART, 1024>>>();
    k_place<<<(n_edges + 255) / 256, 256>>>(ei, ea, n_edges);
    k_nodepre_t<<<592, 128, smem_pre>>>(x, W1, b1);
    k_gather<<<(N_NODES_C + 15) / 16, 256>>>(W1);
    k_out_t<<<592, 128, smem_out>>>(W2, b2, out);
}

// round 5
// speedup vs baseline: 5.5352x; 1.0600x over previous
#include <cuda_runtime.h>

// ---------------------------------------------------------------------------
// GNN edge-MLP + segment-sum, GB300 sm_103a — factored + fixed-cap bucketing
//   P[n] = x[n]@W1[0:64] + b1 ; Q[n] = x[n]@W1[64:128]
//   hid[d] = sum_{active e: dst=d} relu(P[d] + Q[src_e] + ea_e@W1[128:131])
//   out[d] = relu(hid[d]@W2 + cnt[d]*b2)
// Single-pass dst-bucketing into fixed 64-slot rows (deg ~ Poisson(16),
// P(deg>64) < 1e-11 per node), then per-node gather-reduce, no scan/place.
// ---------------------------------------------------------------------------

#define N_NODES_C 100000
#define BCAP 64

__device__ int    g_cnt[N_NODES_C];          // active-edge count per dst
__device__ float  g_thr[N_NODES_C];          // mask threshold per src node
__device__ float4 g_bucket[N_NODES_C * BCAP]; // (e0,e1,e2, src-as-float)
__device__ float  g_P[N_NODES_C * 64];
__device__ float  g_Q[N_NODES_C * 64];
__device__ float  g_hid[N_NODES_C * 64];

// ---- packed f32x2 helpers --------------------------------------------------
__device__ __forceinline__ unsigned long long pk2(float v) {
    unsigned int u = __float_as_uint(v);
    unsigned long long r;
    asm("mov.b64 %0, {%1, %2};" : "=l"(r) : "r"(u), "r"(u));
    return r;
}
__device__ __forceinline__ unsigned long long pkf(float lo, float hi) {
    unsigned long long r;
    asm("mov.b64 %0, {%1, %2};" : "=l"(r)
        : "r"(__float_as_uint(lo)), "r"(__float_as_uint(hi)));
    return r;
}
__device__ __forceinline__ void fma2(unsigned long long& d,
                                     unsigned long long a,
                                     unsigned long long b) {
    asm("fma.rn.f32x2 %0, %1, %2, %0;" : "+l"(d) : "l"(a), "l"(b));
}
__device__ __forceinline__ float2 unpk(unsigned long long v) {
    unsigned int lo, hi;
    asm("mov.b64 {%0, %1}, %2;" : "=r"(lo), "=r"(hi) : "l"(v));
    return make_float2(__uint_as_float(lo), __uint_as_float(hi));
}

// ---- init: zero counts + build mask-threshold table ------------------------
__global__ void k_init(const float* __restrict__ x) {
    int n = blockIdx.x * blockDim.x + threadIdx.x;
    if (n < N_NODES_C) {
        g_cnt[n] = 0;
        float t = __ldg(&x[(size_t)n * 64]);
        g_thr[n] = (t == 0.0f) ? 0.5f
                 : (t == 1.0f) ? 0.3f
                               : __int_as_float(0x7f800000); // +inf
    }
}

// ---- single-pass bucketing: mask + slot-alloc + record write ---------------
// 4 edges per thread, vectorized loads.
__global__ __launch_bounds__(256) void k_bucket(
    const int* __restrict__ ei, const float* __restrict__ ea, int n_edges)
{
    int i = blockIdx.x * blockDim.x + threadIdx.x;   // vector index (4 edges)
    int e0 = i * 4;
    if (e0 >= n_edges) return;

    if (e0 + 3 < n_edges && (n_edges & 3) == 0) {
        int4 s4 = __ldg((const int4*)(ei) + i);
        int4 d4 = __ldg((const int4*)(ei + n_edges) + i);
        float4 a0 = __ldg((const float4*)ea + 3 * i);
        float4 a1 = __ldg((const float4*)ea + 3 * i + 1);
        float4 a2 = __ldg((const float4*)ea + 3 * i + 2);
        // edge j attrs: j0=(a0.x,a0.y,a0.z) j1=(a0.w,a1.x,a1.y)
        //              j2=(a1.z,a1.w,a2.x) j3=(a2.y,a2.z,a2.w)
        int   ss[4] = {s4.x, s4.y, s4.z, s4.w};
        int   dd[4] = {d4.x, d4.y, d4.z, d4.w};
        float ex[4] = {a0.x, a0.w, a1.z, a2.y};
        float ey[4] = {a0.y, a1.x, a1.w, a2.z};
        float ez[4] = {a0.z, a1.y, a2.x, a2.w};
#pragma unroll
        for (int j = 0; j < 4; j++) {
            float thr = __ldg(g_thr + ss[j]);
            if (ex[j] < thr) {
                int slot = atomicAdd(g_cnt + dd[j], 1);
                if (slot < BCAP)
                    g_bucket[(size_t)dd[j] * BCAP + slot] =
                        make_float4(ex[j], ey[j], ez[j], __int_as_float(ss[j]));
            }
        }
    } else {
        for (int e = e0; e < e0 + 4 && e < n_edges; e++) {
            int src = __ldg(ei + e);
            int dst = __ldg(ei + n_edges + e);
            const float* er = ea + (size_t)e * 3;
            float d0 = __ldg(er);
            float thr = __ldg(g_thr + src);
            if (d0 < thr) {
                int slot = atomicAdd(g_cnt + dst, 1);
                if (slot < BCAP)
                    g_bucket[(size_t)dst * BCAP + slot] =
                        make_float4(d0, __ldg(er + 1), __ldg(er + 2),
                                    __int_as_float(src));
            }
        }
    }
}

// ---------------------------------------------------------------------------
// Node precompute GEMM: [P|Q][64 nodes x 128] = X[64x64] @ Wc[64x128]
// ---------------------------------------------------------------------------
__global__ __launch_bounds__(128) void k_nodepre_t(
    const float* __restrict__ x, const float* __restrict__ W1,
    const float* __restrict__ b1)
{
    extern __shared__ float sm[];
    float* Wc = sm;            // 64*128
    float* Xt = Wc + 64 * 128; // 64k x 64n

    const int tid = threadIdx.x;
    for (int idx = tid; idx < 64 * 128; idx += 128) {
        int k = idx >> 7, j = idx & 127;
        Wc[idx] = (j < 64) ? W1[k * 64 + j] : W1[(64 + k) * 64 + (j - 64)];
    }
    __syncthreads();

    const int tn = tid & 7, te = tid >> 3;
    const int n_loc = tid & 63, c = tid >> 6;

    unsigned long long b1p[4];
    b1p[0] = pkf(__ldg(&b1[tn * 4 + 0]), __ldg(&b1[tn * 4 + 1]));
    b1p[1] = pkf(__ldg(&b1[tn * 4 + 2]), __ldg(&b1[tn * 4 + 3]));
    b1p[2] = pkf(__ldg(&b1[32 + tn * 4 + 0]), __ldg(&b1[32 + tn * 4 + 1]));
    b1p[3] = pkf(__ldg(&b1[32 + tn * 4 + 2]), __ldg(&b1[32 + tn * 4 + 3]));

    const int n_tiles = (N_NODES_C + 63) / 64;

    for (int tile = blockIdx.x; tile < n_tiles; tile += gridDim.x) {
        const int base = tile * 64;
        int nt = N_NODES_C - base;
        if (nt > 64) nt = 64;

        __syncthreads();
        {
            int n = base + ((n_loc < nt) ? n_loc : 0);
            const float4* xr = (const float4*)(x + (size_t)n * 64) + c * 8;
#pragma unroll
            for (int q = 0; q < 8; q++) {
                float4 v = __ldg(&xr[q]);
                int k0 = c * 32 + q * 4;
                Xt[(k0 + 0) * 64 + n_loc] = v.x;
                Xt[(k0 + 1) * 64 + n_loc] = v.y;
                Xt[(k0 + 2) * 64 + n_loc] = v.z;
                Xt[(k0 + 3) * 64 + n_loc] = v.w;
            }
        }
        __syncthreads();

#pragma unroll
        for (int half = 0; half < 2; half++) {
            unsigned long long acc[4][4];
#pragma unroll
            for (int e = 0; e < 4; e++)
#pragma unroll
                for (int p = 0; p < 4; p++)
                    acc[e][p] = half ? 0ull : b1p[p];

#pragma unroll 4
            for (int k = 0; k < 64; k++) {
                float4 h4 = *(const float4*)(Xt + k * 64 + te * 4);
                const float* wrow = Wc + k * 128 + half * 64;
                ulonglong2 wA = *(const ulonglong2*)(wrow + tn * 4);
                ulonglong2 wB = *(const ulonglong2*)(wrow + 32 + tn * 4);
                unsigned long long hd0 = pk2(h4.x), hd1 = pk2(h4.y),
                                   hd2 = pk2(h4.z), hd3 = pk2(h4.w);
                fma2(acc[0][0], hd0, wA.x); fma2(acc[0][1], hd0, wA.y);
                fma2(acc[0][2], hd0, wB.x); fma2(acc[0][3], hd0, wB.y);
                fma2(acc[1][0], hd1, wA.x); fma2(acc[1][1], hd1, wA.y);
                fma2(acc[1][2], hd1, wB.x); fma2(acc[1][3], hd1, wB.y);
                fma2(acc[2][0], hd2, wA.x); fma2(acc[2][1], hd2, wA.y);
                fma2(acc[2][2], hd2, wB.x); fma2(acc[2][3], hd2, wB.y);
                fma2(acc[3][0], hd3, wA.x); fma2(acc[3][1], hd3, wA.y);
                fma2(acc[3][2], hd3, wB.x); fma2(acc[3][3], hd3, wB.y);
            }

            float* dstbuf = half ? g_Q : g_P;
#pragma unroll
            for (int e = 0; e < 4; e++) {
                int nl = te * 4 + e;
                if (nl < nt) {
                    float* op = dstbuf + (size_t)(base + nl) * 64;
#pragma unroll
                    for (int p = 0; p < 4; p++) {
                        float2 v = unpk(acc[e][p]);
                        int cc = (p < 2) ? (tn * 4 + p * 2)
                                         : (32 + tn * 4 + (p - 2) * 2);
                        *(float2*)(op + cc) = v;
                    }
                }
            }
        }
    }
}

// ---- gather-reduce: hid[d] = sum relu(P[d]+Q[src]+ea@W1c) ------------------
// 16 threads per node (cg -> 4 cols), 16 nodes per 256-thread block.
__global__ __launch_bounds__(256) void k_gather(const float* __restrict__ W1)
{
    __shared__ float wc[3 * 64];
    int tid = threadIdx.x;
    if (tid < 192) wc[tid] = W1[128 * 64 + tid];
    __syncthreads();

    int cg = tid & 15;
    int node = blockIdx.x * 16 + (tid >> 4);
    if (node >= N_NODES_C) return;

    float wcr[3][4];
#pragma unroll
    for (int r = 0; r < 3; r++)
#pragma unroll
        for (int j = 0; j < 4; j++) wcr[r][j] = wc[r * 64 + cg * 4 + j];

    int cnt = g_cnt[node];
    if (cnt > BCAP) cnt = BCAP;
    const float4* brow = g_bucket + (size_t)node * BCAP;
    float4 p = ((const float4*)(g_P + (size_t)node * 64))[cg];
    float a0 = 0.f, a1 = 0.f, a2 = 0.f, a3 = 0.f;

    int e = 0;
    for (; e + 4 <= cnt; e += 4) {
        float4 r0 = __ldg(brow + e);
        float4 r1 = __ldg(brow + e + 1);
        float4 r2 = __ldg(brow + e + 2);
        float4 r3 = __ldg(brow + e + 3);
        float4 q0 = ((const float4*)(g_Q + (size_t)__float_as_int(r0.w) * 64))[cg];
        float4 q1 = ((const float4*)(g_Q + (size_t)__float_as_int(r1.w) * 64))[cg];
        float4 q2 = ((const float4*)(g_Q + (size_t)__float_as_int(r2.w) * 64))[cg];
        float4 q3 = ((const float4*)(g_Q + (size_t)__float_as_int(r3.w) * 64))[cg];
#pragma unroll
        for (int u = 0; u < 4; u++) {
            float4 R = (u == 0) ? r0 : (u == 1) ? r1 : (u == 2) ? r2 : r3;
            float4 Qv = (u == 0) ? q0 : (u == 1) ? q1 : (u == 2) ? q2 : q3;
            float t0 = p.x + Qv.x, t1 = p.y + Qv.y,
                  t2 = p.z + Qv.z, t3 = p.w + Qv.w;
            t0 = fmaf(R.x, wcr[0][0], fmaf(R.y, wcr[1][0], fmaf(R.z, wcr[2][0], t0)));
            t1 = fmaf(R.x, wcr[0][1], fmaf(R.y, wcr[1][1], fmaf(R.z, wcr[2][1], t1)));
            t2 = fmaf(R.x, wcr[0][2], fmaf(R.y, wcr[1][2], fmaf(R.z, wcr[2][2], t2)));
            t3 = fmaf(R.x, wcr[0][3], fmaf(R.y, wcr[1][3], fmaf(R.z, wcr[2][3], t3)));
            a0 += fmaxf(t0, 0.f); a1 += fmaxf(t1, 0.f);
            a2 += fmaxf(t2, 0.f); a3 += fmaxf(t3, 0.f);
        }
    }
    for (; e < cnt; e++) {
        float4 R = __ldg(brow + e);
        float4 Qv = ((const float4*)(g_Q + (size_t)__float_as_int(R.w) * 64))[cg];
        float t0 = p.x + Qv.x, t1 = p.y + Qv.y,
              t2 = p.z + Qv.z, t3 = p.w + Qv.w;
        t0 = fmaf(R.x, wcr[0][0], fmaf(R.y, wcr[1][0], fmaf(R.z, wcr[2][0], t0)));
        t1 = fmaf(R.x, wcr[0][1], fmaf(R.y, wcr[1][1], fmaf(R.z, wcr[2][1], t1)));
        t2 = fmaf(R.x, wcr[0][2], fmaf(R.y, wcr[1][2], fmaf(R.z, wcr[2][2], t2)));
        t3 = fmaf(R.x, wcr[0][3], fmaf(R.y, wcr[1][3], fmaf(R.z, wcr[2][3], t3)));
        a0 += fmaxf(t0, 0.f); a1 += fmaxf(t1, 0.f);
        a2 += fmaxf(t2, 0.f); a3 += fmaxf(t3, 0.f);
    }

    ((float4*)(g_hid + (size_t)node * 64))[cg] = make_float4(a0, a1, a2, a3);
}

// ---------------------------------------------------------------------------
// Output GEMM: out[64 nodes x 128] = relu(Hid[64x64] @ W2 + cnt*b2)
// ---------------------------------------------------------------------------
__global__ __launch_bounds__(128) void k_out_t(
    const float* __restrict__ W2, const float* __restrict__ b2,
    float* __restrict__ out)
{
    extern __shared__ float sm[];
    float* W2s = sm;             // 64*128
    float* Ht  = W2s + 64 * 128; // 64k x 64n
    float* cs  = Ht + 64 * 64;   // 64 counts
    float* b2s = cs + 64;        // 128

    const int tid = threadIdx.x;
    for (int idx = tid; idx < 64 * 128; idx += 128) W2s[idx] = W2[idx];
    b2s[tid] = b2[tid];
    __syncthreads();

    const int tn = tid & 7, te = tid >> 3;
    const int n_loc = tid & 63, c = tid >> 6;
    const int n_tiles = (N_NODES_C + 63) / 64;

    for (int tile = blockIdx.x; tile < n_tiles; tile += gridDim.x) {
        const int base = tile * 64;
        int nt = N_NODES_C - base;
        if (nt > 64) nt = 64;

        __syncthreads();
        {
            int n = base + ((n_loc < nt) ? n_loc : 0);
            const float4* hr = (const float4*)(g_hid + (size_t)n * 64) + c * 8;
#pragma unroll
            for (int q = 0; q < 8; q++) {
                float4 v = hr[q];
                int k0 = c * 32 + q * 4;
                Ht[(k0 + 0) * 64 + n_loc] = v.x;
                Ht[(k0 + 1) * 64 + n_loc] = v.y;
                Ht[(k0 + 2) * 64 + n_loc] = v.z;
                Ht[(k0 + 3) * 64 + n_loc] = v.w;
            }
            if (c == 0) {
                int cv = (n_loc < nt) ? g_cnt[base + n_loc] : 0;
                if (cv > BCAP) cv = BCAP;
                cs[n_loc] = (float)cv;
            }
        }
        __syncthreads();

#pragma unroll
        for (int half = 0; half < 2; half++) {
            unsigned long long acc[4][4];
#pragma unroll
            for (int e = 0; e < 4; e++)
#pragma unroll
                for (int p = 0; p < 4; p++) acc[e][p] = 0ull;

#pragma unroll 4
            for (int k = 0; k < 64; k++) {
                float4 h4 = *(const float4*)(Ht + k * 64 + te * 4);
                const float* wrow = W2s + k * 128 + half * 64;
                ulonglong2 wA = *(const ulonglong2*)(wrow + tn * 4);
                ulonglong2 wB = *(const ulonglong2*)(wrow + 32 + tn * 4);
                unsigned long long hd0 = pk2(h4.x), hd1 = pk2(h4.y),
                                   hd2 = pk2(h4.z), hd3 = pk2(h4.w);
                fma2(acc[0][0], hd0, wA.x); fma2(acc[0][1], hd0, wA.y);
                fma2(acc[0][2], hd0, wB.x); fma2(acc[0][3], hd0, wB.y);
                fma2(acc[1][0], hd1, wA.x); fma2(acc[1][1], hd1, wA.y);
                fma2(acc[1][2], hd1, wB.x); fma2(acc[1][3], hd1, wB.y);
                fma2(acc[2][0], hd2, wA.x); fma2(acc[2][1], hd2, wA.y);
                fma2(acc[2][2], hd2, wB.x); fma2(acc[2][3], hd2, wB.y);
                fma2(acc[3][0], hd3, wA.x); fma2(acc[3][1], hd3, wA.y);
                fma2(acc[3][2], hd3, wB.x); fma2(acc[3][3], hd3, wB.y);
            }

#pragma unroll
            for (int e = 0; e < 4; e++) {
                int nl = te * 4 + e;
                if (nl < nt) {
                    float cf = cs[nl];
                    float* op = out + (size_t)(base + nl) * 128 + half * 64;
#pragma unroll
                    for (int p = 0; p < 4; p++) {
                        float2 v = unpk(acc[e][p]);
                        int cc = (p < 2) ? (tn * 4 + p * 2)
                                         : (32 + tn * 4 + (p - 2) * 2);
                        float2 r;
                        r.x = fmaxf(v.x + cf * b2s[half * 64 + cc], 0.0f);
                        r.y = fmaxf(v.y + cf * b2s[half * 64 + cc + 1], 0.0f);
                        *(float2*)(op + cc) = r;
                    }
                }
            }
        }
    }
}

// ---------------------------------------------------------------------------
extern "C" void kernel_launch(void* const* d_in, const int* in_sizes, int n_in,
                              void* d_out, int out_size) {
    const float* x  = (const float*)d_in[0];
    const int*   ei = (const int*)d_in[1];
    const float* ea = (const float*)d_in[2];
    const float* W1 = (const float*)d_in[3];
    const float* b1 = (const float*)d_in[4];
    const float* W2 = (const float*)d_in[5];
    const float* b2 = (const float*)d_in[6];
    float* out = (float*)d_out;

    const int n_edges = in_sizes[1] / 2;

    const int smem_pre = (64 * 128 + 64 * 64) * 4;
    const int smem_out = (64 * 128 + 64 * 64 + 64 + 128) * 4;
    cudaFuncSetAttribute(k_nodepre_t,
                         cudaFuncAttributeMaxDynamicSharedMemorySize, smem_pre);
    cudaFuncSetAttribute(k_out_t,
                         cudaFuncAttributeMaxDynamicSharedMemorySize, smem_out);

    k_init<<<(N_NODES_C + 255) / 256, 256>>>(x);
    k_bucket<<<(n_edges / 4 + 255) / 256, 256>>>(ei, ea, n_edges);
    k_nodepre_t<<<592, 128, smem_pre>>>(x, W1, b1);
    k_gather<<<(N_NODES_C + 15) / 16, 256>>>(W1);
    k_out_t<<<592, 128, smem_out>>>(W2, b2, out);
}